// round 6
// baseline (speedup 1.0000x reference)
#include <cuda_runtime.h>
#include <cuda.h>
#include <cuda_fp16.h>
#include <cstdint>

// ---------------- problem constants ----------------
#define NNODES 16384
#define DIM    128
#define KC     32                          // K per chunk
#define CHUNKS (NNODES / KC)               // 512
#define STAGES 3
#define MTILE  64                          // CTA rows (3 CTAs/SM)

// B (zh) padded chunk layout: [chunk][o:128][40 halves] (32 data + 8 pad, 80B rows)
#define BROW_H   40
#define BROW_B   80
#define BCHUNK_H (DIM * BROW_H)            // 5120 halves = 10240 B
#define BCHUNK_B (BCHUNK_H * 2)

#define A32_BYTES (MTILE * KC * 4)         // 8192 B per stage (SW128 swizzled fp32)
#define A16_ROWB  80                       // padded fp16 A row stride
#define A16_BYTES (MTILE * A16_ROWB)       // 5120 B per ping buffer
#define TXB (A32_BYTES + BCHUNK_B)         // 18432

// smem layout (gemm kernel)
#define SM_MBAR 0
#define SM_A32  1024
#define SM_B    (1024 + STAGES * A32_BYTES)              // 25600
#define SM_A16  (SM_B + STAGES * BCHUNK_B)               // 56320
#define GEMM_SMEM (SM_A16 + 2 * A16_BYTES)               // 66560  -> 3 CTAs/SM

// scratch (__device__ globals: allocation-free rule)
__device__ __half g_zh[CHUNKS * BCHUNK_H];   // 5 MB, padded-chunk layout
__device__ float  g_u [NNODES * DIM];        // 8 MB: x@W1^T + b

// ---------------- PTX helpers (compute_103-baseline only) ----------------
__device__ __forceinline__ uint32_t smem_u32(const void* p) {
    uint32_t a;
    asm("{ .reg .u64 t; cvta.to.shared.u64 t, %1; cvt.u32.u64 %0, t; }" : "=r"(a) : "l"(p));
    return a;
}
__device__ __forceinline__ void mbar_init(uint32_t mbar, uint32_t cnt) {
    asm volatile("mbarrier.init.shared.b64 [%0], %1;" :: "r"(mbar), "r"(cnt) : "memory");
}
__device__ __forceinline__ void mbar_expect_tx(uint32_t mbar, uint32_t bytes) {
    asm volatile("mbarrier.arrive.expect_tx.shared.b64 _, [%0], %1;" :: "r"(mbar), "r"(bytes) : "memory");
}
__device__ __forceinline__ void mbar_wait(uint32_t mbar, uint32_t parity) {
    asm volatile(
        "{\n\t.reg .pred P;\n\t"
        "W_%=:\n\t"
        "mbarrier.try_wait.parity.shared.b64 P, [%0], %1, 0x989680;\n\t"
        "@P bra D_%=;\n\t"
        "bra W_%=;\n\t"
        "D_%=:\n\t}"
        :: "r"(mbar), "r"(parity) : "memory");
}
__device__ __forceinline__ void tma_2d(uint32_t dst, const CUtensorMap* map,
                                       int cx, int cy, uint32_t mbar) {
    asm volatile(
        "cp.async.bulk.tensor.2d.shared::cta.global.tile.mbarrier::complete_tx::bytes "
        "[%0], [%1, {%2, %3}], [%4];"
        :: "r"(dst), "l"(map), "r"(cx), "r"(cy), "r"(mbar) : "memory");
}
__device__ __forceinline__ void bulk_cp(uint32_t dst, const void* src, uint32_t bytes, uint32_t mbar) {
    asm volatile(
        "cp.async.bulk.shared::cta.global.mbarrier::complete_tx::bytes [%0], [%1], %2, [%3];"
        :: "r"(dst), "l"(src), "r"(bytes), "r"(mbar) : "memory");
}
__device__ __forceinline__ void ldm_x4(uint32_t* r, uint32_t addr) {
    asm volatile("ldmatrix.sync.aligned.m8n8.x4.shared.b16 {%0,%1,%2,%3}, [%4];"
        : "=r"(r[0]), "=r"(r[1]), "=r"(r[2]), "=r"(r[3]) : "r"(addr));
}
__device__ __forceinline__ void mma16816(float* c, const uint32_t* a, const uint32_t* b) {
    asm volatile("mma.sync.aligned.m16n8k16.row.col.f32.f16.f16.f32 "
        "{%0,%1,%2,%3}, {%4,%5,%6,%7}, {%8,%9}, {%0,%1,%2,%3};"
        : "+f"(c[0]), "+f"(c[1]), "+f"(c[2]), "+f"(c[3])
        : "r"(a[0]), "r"(a[1]), "r"(a[2]), "r"(a[3]), "r"(b[0]), "r"(b[1]));
}

// fp32 SW128 stage (64 rows x 128B) -> padded fp16 ping buffer (256 threads)
__device__ __forceinline__ void convert_chunk(const char* a32, char* a16, int tid) {
    const int crow = tid >> 2, q = tid & 3;
    const uint32_t rsw = (uint32_t)(crow & 7) << 4;
    const uint32_t b0 = (uint32_t)(crow * 128 + q * 32);
    float4 v0 = *reinterpret_cast<const float4*>(a32 + (b0 ^ rsw));
    float4 v1 = *reinterpret_cast<const float4*>(a32 + ((b0 + 16) ^ rsw));
    __half2 h0 = __floats2half2_rn(v0.x, v0.y);
    __half2 h1 = __floats2half2_rn(v0.z, v0.w);
    __half2 h2 = __floats2half2_rn(v1.x, v1.y);
    __half2 h3 = __floats2half2_rn(v1.z, v1.w);
    uint4 pk;
    pk.x = *reinterpret_cast<uint32_t*>(&h0);
    pk.y = *reinterpret_cast<uint32_t*>(&h1);
    pk.z = *reinterpret_cast<uint32_t*>(&h2);
    pk.w = *reinterpret_cast<uint32_t*>(&h3);
    *reinterpret_cast<uint4*>(a16 + crow * A16_ROWB + q * 16) = pk;
}

// ============================================================================
// Kernel 1 (prep): 128 CTAs x 512 threads, 128 nodes/CTA, single wave.
//   z[m][o] = sum_d x[m][d] * W[o][128+d]  -> fp16, padded chunk layout g_zh
//   u[m][o] = sum_d x[m][d] * W[o][d] + b[o] -> fp32 g_u
// ============================================================================
#define PREP_SMEM ((128 * DIM + 256 * 129) * 4 + 128 * 128 * 2)   // 230400

__global__ __launch_bounds__(512) void prep_kernel(const float* __restrict__ x,
                                                   const float* __restrict__ W,
                                                   const float* __restrict__ b) {
    extern __shared__ float sm1[];
    float*  xs  = sm1;                              // [128][128]
    float*  ws  = sm1 + 128 * DIM;                  // [256][129]
    __half* zsm = (__half*)(sm1 + 128 * DIM + 256 * 129);  // [128 o][128 node]
    const int tid = threadIdx.x;
    const int node0 = blockIdx.x * 128;

    const float4* xg = reinterpret_cast<const float4*>(x + (size_t)node0 * DIM);
    float4* xs4 = reinterpret_cast<float4*>(xs);
    #pragma unroll
    for (int i = tid; i < 128 * DIM / 4; i += 512) xs4[i] = xg[i];

    for (int idx = tid; idx < 256 * DIM; idx += 512) {
        int j = idx >> 7, k = idx & 127;
        float v = (j < DIM) ? W[j * 256 + DIM + k] : W[(j - DIM) * 256 + k];
        ws[j * 129 + k] = v;
    }
    __syncthreads();

    const int ng = tid >> 4;   // 0..31 -> nodes 4*ng .. 4*ng+3
    const int og = tid & 15;
    float acc[64];
    #pragma unroll
    for (int i = 0; i < 64; i++) acc[i] = 0.f;

    #pragma unroll 4
    for (int k = 0; k < DIM; ++k) {
        float xv[4];
        #pragma unroll
        for (int i = 0; i < 4; i++) xv[i] = xs[(4 * ng + i) * DIM + k];
        #pragma unroll
        for (int q = 0; q < 4; q++) {
            #pragma unroll
            for (int r = 0; r < 4; r++) {
                float wv = ws[(4 * og + 64 * q + r) * 129 + k];
                #pragma unroll
                for (int i = 0; i < 4; i++)
                    acc[i * 16 + 4 * q + r] = fmaf(xv[i], wv, acc[i * 16 + 4 * q + r]);
            }
        }
    }

    float4 bq0 = *reinterpret_cast<const float4*>(b + 4 * og);
    float4 bq1 = *reinterpret_cast<const float4*>(b + 4 * og + 64);

    #pragma unroll
    for (int i = 0; i < 4; i++) {
        int mloc = 4 * ng + i;
        #pragma unroll
        for (int q = 0; q < 2; q++)
            #pragma unroll
            for (int r = 0; r < 4; r++) {
                int j = 4 * og + 64 * q + r;
                zsm[j * 128 + mloc] = __float2half_rn(acc[i * 16 + 4 * q + r]);
            }
        float4 u0, u1;
        u0.x = acc[i*16+8] + bq0.x;  u0.y = acc[i*16+9] + bq0.y;
        u0.z = acc[i*16+10] + bq0.z; u0.w = acc[i*16+11] + bq0.w;
        u1.x = acc[i*16+12] + bq1.x; u1.y = acc[i*16+13] + bq1.y;
        u1.z = acc[i*16+14] + bq1.z; u1.w = acc[i*16+15] + bq1.w;
        *reinterpret_cast<float4*>(g_u + (size_t)(node0 + mloc) * DIM + 4 * og)      = u0;
        *reinterpret_cast<float4*>(g_u + (size_t)(node0 + mloc) * DIM + 4 * og + 64) = u1;
    }
    __syncthreads();

    {
        int o = tid >> 2, q = tid & 3;
        int c0 = blockIdx.x * 4;
        const uint4* src = reinterpret_cast<const uint4*>(zsm + o * 128 + q * 32);
        __half* dstp = g_zh + (size_t)(c0 + q) * BCHUNK_H + o * BROW_H;
        uint4* dst = reinterpret_cast<uint4*>(dstp);
        #pragma unroll
        for (int i = 0; i < 4; i++) dst[i] = src[i];
    }
}

// ============================================================================
// Kernel 2 (main): 256 CTAs x 256 threads, 3 CTAs/SM (66.5KB smem each).
//   CTA tile 64x128; warp grid 2(M) x 4(N), warp tile 32x32.
//   Software-pipelined fp32->fp16 convert (ping-pong), one barrier per iter.
// ============================================================================
__global__ void __launch_bounds__(256, 3) gemm_kernel(
    const __grid_constant__ CUtensorMap tma_a,
    float* __restrict__ out) {
    extern __shared__ char smem[];
    const uint32_t sb = smem_u32(smem);
    const uint32_t MB = sb + SM_MBAR;

    const int tid  = threadIdx.x;
    const int lane = tid & 31;
    const int w    = tid >> 5;
    const int m0g  = blockIdx.x * MTILE;
    const int m0w  = (w >> 2) * 32;     // warp tile 32x32
    const int n0w  = (w & 3) * 32;

    if (tid == 0) {
        #pragma unroll
        for (int s = 0; s < STAGES; ++s) mbar_init(MB + 8 * s, 1);
    }
    __syncthreads();

    if (tid == 0) {
        #pragma unroll
        for (int s = 0; s < STAGES; ++s) {
            mbar_expect_tx(MB + 8 * s, TXB);
            tma_2d(sb + SM_A32 + s * A32_BYTES, &tma_a, s * KC, m0g, MB + 8 * s);
            bulk_cp(sb + SM_B + s * BCHUNK_B, g_zh + (size_t)s * BCHUNK_H, BCHUNK_B, MB + 8 * s);
        }
    }

    // A ldmatrix offsets (from padded fp16 ping buffer)
    uint32_t aoff[2];
    #pragma unroll
    for (int mi = 0; mi < 2; ++mi)
        aoff[mi] = (uint32_t)((m0w + mi * 16 + (lane & 15)) * A16_ROWB + (lane >> 4) * 16);
    // B ldmatrix offset (padded 80B rows)
    const int bg = lane >> 3;
    const uint32_t boff =
        (uint32_t)((n0w + ((bg >> 1) & 1) * 8 + (lane & 7)) * BROW_B + (bg & 1) * 16);

    float acc[2][4][4];
    #pragma unroll
    for (int i = 0; i < 2; i++)
        #pragma unroll
        for (int j = 0; j < 4; j++)
            #pragma unroll
            for (int k = 0; k < 4; k++) acc[i][j][k] = 0.f;

    // prologue: convert chunk 0 into ping[0]
    mbar_wait(MB + 8 * 0, 0);
    convert_chunk(smem + SM_A32 + 0 * A32_BYTES, smem + SM_A16 + 0 * A16_BYTES, tid);
    __syncthreads();

    int s = 0, ph = 0;
    #pragma unroll 1
    for (int it = 0; it < CHUNKS; ++it) {
        const uint32_t bst  = sb + SM_B + s * BCHUNK_B;
        const uint32_t a16b = sb + SM_A16 + (uint32_t)(it & 1) * A16_BYTES;

        // --- pre-barrier: all fragment loads for chunk it ---
        uint32_t bfr[2][2][4];
        #pragma unroll
        for (int nt2 = 0; nt2 < 2; ++nt2)
            #pragma unroll
            for (int ks = 0; ks < 2; ++ks)
                ldm_x4(bfr[nt2][ks], bst + boff + nt2 * 16 * BROW_B + ks * 32);

        uint32_t afr[2][2][4];
        #pragma unroll
        for (int ks = 0; ks < 2; ++ks)
            #pragma unroll
            for (int mi = 0; mi < 2; ++mi)
                ldm_x4(afr[ks][mi], a16b + aoff[mi] + ks * 32);

        // --- pre-barrier: convert chunk it+1 into the other ping buffer ---
        if (it + 1 < CHUNKS) {
            int sn  = (s + 1 == STAGES) ? 0 : s + 1;
            int phn = (s + 1 == STAGES) ? (ph ^ 1) : ph;
            mbar_wait(MB + 8 * sn, phn);
            convert_chunk(smem + SM_A32 + sn * A32_BYTES,
                          smem + SM_A16 + ((it + 1) & 1) * A16_BYTES, tid);
        }

        __syncthreads();

        // --- post-barrier: refill stage s ---
        if (tid == 0) {
            int nxt = it + STAGES;
            if (nxt < CHUNKS) {
                mbar_expect_tx(MB + 8 * s, TXB);
                tma_2d(sb + SM_A32 + s * A32_BYTES, &tma_a, nxt * KC, m0g, MB + 8 * s);
                bulk_cp(sb + SM_B + s * BCHUNK_B, g_zh + (size_t)nxt * BCHUNK_H,
                        BCHUNK_B, MB + 8 * s);
            }
        }

        // --- post-barrier: MMAs (register-only) ---
        #pragma unroll
        for (int ks = 0; ks < 2; ++ks)
            #pragma unroll
            for (int mi = 0; mi < 2; ++mi)
                #pragma unroll
                for (int nt = 0; nt < 4; ++nt)
                    mma16816(acc[mi][nt], afr[ks][mi], &bfr[nt >> 1][ks][(nt & 1) * 2]);

        if (++s == STAGES) { s = 0; ph ^= 1; }
    }

    // --- epilogue: += u, ReLU, store ---
    #pragma unroll
    for (int mi = 0; mi < 2; ++mi) {
        int r = m0w + mi * 16 + (lane >> 2);
        #pragma unroll
        for (int nt = 0; nt < 4; ++nt) {
            int c = n0w + nt * 8 + 2 * (lane & 3);
            size_t i0 = (size_t)(m0g + r) * DIM + c;
            float2 u0 = *reinterpret_cast<const float2*>(g_u + i0);
            float2 u1 = *reinterpret_cast<const float2*>(g_u + i0 + 8 * DIM);
            const float* a = acc[mi][nt];
            float2 o0, o1;
            o0.x = fmaxf(a[0] + u0.x, 0.f); o0.y = fmaxf(a[1] + u0.y, 0.f);
            o1.x = fmaxf(a[2] + u1.x, 0.f); o1.y = fmaxf(a[3] + u1.y, 0.f);
            *reinterpret_cast<float2*>(out + i0)           = o0;
            *reinterpret_cast<float2*>(out + i0 + 8 * DIM) = o1;
        }
    }
}

// ============================================================================
// Host launch
// ============================================================================
typedef CUresult (*EncodeFn)(CUtensorMap*, CUtensorMapDataType, cuuint32_t, void*,
                             const cuuint64_t*, const cuuint64_t*, const cuuint32_t*,
                             const cuuint32_t*, CUtensorMapInterleave, CUtensorMapSwizzle,
                             CUtensorMapL2promotion, CUtensorMapFloatOOBfill);

extern "C" void kernel_launch(void* const* d_in, const int* in_sizes, int n_in,
                              void* d_out, int out_size) {
    const float *x = nullptr, *adj = nullptr, *W = nullptr, *b = nullptr;
    for (int i = 0; i < n_in; ++i) {
        switch (in_sizes[i]) {
            case NNODES * DIM: x = (const float*)d_in[i]; break;
            case 32768:        W = (const float*)d_in[i]; break;
            case 128:          b = (const float*)d_in[i]; break;
            default:           adj = (const float*)d_in[i]; break;
        }
    }
    float* out = (float*)d_out;

    void* fn = nullptr;
    cudaDriverEntryPointQueryResult qr;
#if CUDART_VERSION >= 12050
    cudaGetDriverEntryPointByVersion("cuTensorMapEncodeTiled", &fn, 12000,
                                     cudaEnableDefault, &qr);
#else
    cudaGetDriverEntryPoint("cuTensorMapEncodeTiled", &fn, cudaEnableDefault, &qr);
#endif
    if (!fn) return;
    EncodeFn encode = (EncodeFn)fn;

    CUtensorMap mapA;
    {
        cuuint64_t dims[2]   = {NNODES, NNODES};
        cuuint64_t stride[1] = {NNODES * 4ull};
        cuuint32_t box[2]    = {KC, MTILE};        // 128B x 64 rows, SW128
        cuuint32_t es[2]     = {1, 1};
        encode(&mapA, CU_TENSOR_MAP_DATA_TYPE_FLOAT32, 2, (void*)adj, dims, stride, box, es,
               CU_TENSOR_MAP_INTERLEAVE_NONE, CU_TENSOR_MAP_SWIZZLE_128B,
               CU_TENSOR_MAP_L2_PROMOTION_L2_128B, CU_TENSOR_MAP_FLOAT_OOB_FILL_NONE);
    }

    cudaFuncSetAttribute(prep_kernel, cudaFuncAttributeMaxDynamicSharedMemorySize, PREP_SMEM);
    cudaFuncSetAttribute(gemm_kernel, cudaFuncAttributeMaxDynamicSharedMemorySize, GEMM_SMEM);

    prep_kernel<<<NNODES / 128, 512, PREP_SMEM>>>(x, W, b);
    gemm_kernel<<<NNODES / MTILE, 256, GEMM_SMEM>>>(mapA, out);
}

// round 7
// speedup vs baseline: 1.1762x; 1.1762x over previous
#include <cuda_runtime.h>
#include <cuda.h>
#include <cuda_fp16.h>
#include <cstdint>

// ---------------- problem constants ----------------
#define NNODES 16384
#define DIM    128
#define KC     32                          // K per chunk
#define CHUNKS (NNODES / KC)               // 512
#define KSPLIT 2
#define SEG_CHUNKS (CHUNKS / KSPLIT)       // 256 chunks per CTA
#define STAGES 5
#define MTILE  64

// B (zh) padded chunk layout: [chunk][o:128][40 halves] (32 data + 8 pad, 80B rows)
#define BROW_H   40
#define BROW_B   80
#define BCHUNK_H (DIM * BROW_H)            // 5120 halves = 10240 B
#define BCHUNK_B (BCHUNK_H * 2)

#define A32_BYTES (MTILE * KC * 4)         // 8192 B per stage (SW128 swizzled fp32)
#define A16_ROWB  80                       // padded fp16 A row stride
#define A16_BYTES (MTILE * A16_ROWB)       // 5120 B per ping buffer
#define TXB (A32_BYTES + BCHUNK_B)         // 18432

// smem layout (gemm kernel)
#define SM_MBAR 0
#define SM_A32  1024
#define SM_B    (1024 + STAGES * A32_BYTES)              // 41984
#define SM_A16  (SM_B + STAGES * BCHUNK_B)               // 93184
#define GEMM_SMEM (SM_A16 + 2 * A16_BYTES)               // 103424 -> 2 CTAs/SM

// scratch (__device__ globals: allocation-free rule)
__device__ __half g_zh[CHUNKS * BCHUNK_H];       // 5 MB, padded-chunk layout
__device__ float  g_u [NNODES * DIM];            // 8 MB: x@W1^T + b
__device__ float  g_part[KSPLIT * NNODES * DIM]; // 16 MB split-K partials

// ---------------- PTX helpers (compute_103-baseline only) ----------------
__device__ __forceinline__ uint32_t smem_u32(const void* p) {
    uint32_t a;
    asm("{ .reg .u64 t; cvta.to.shared.u64 t, %1; cvt.u32.u64 %0, t; }" : "=r"(a) : "l"(p));
    return a;
}
__device__ __forceinline__ void mbar_init(uint32_t mbar, uint32_t cnt) {
    asm volatile("mbarrier.init.shared.b64 [%0], %1;" :: "r"(mbar), "r"(cnt) : "memory");
}
__device__ __forceinline__ void mbar_expect_tx(uint32_t mbar, uint32_t bytes) {
    asm volatile("mbarrier.arrive.expect_tx.shared.b64 _, [%0], %1;" :: "r"(mbar), "r"(bytes) : "memory");
}
__device__ __forceinline__ void mbar_wait(uint32_t mbar, uint32_t parity) {
    asm volatile(
        "{\n\t.reg .pred P;\n\t"
        "W_%=:\n\t"
        "mbarrier.try_wait.parity.shared.b64 P, [%0], %1, 0x989680;\n\t"
        "@P bra D_%=;\n\t"
        "bra W_%=;\n\t"
        "D_%=:\n\t}"
        :: "r"(mbar), "r"(parity) : "memory");
}
__device__ __forceinline__ void tma_2d(uint32_t dst, const CUtensorMap* map,
                                       int cx, int cy, uint32_t mbar) {
    asm volatile(
        "cp.async.bulk.tensor.2d.shared::cta.global.tile.mbarrier::complete_tx::bytes "
        "[%0], [%1, {%2, %3}], [%4];"
        :: "r"(dst), "l"(map), "r"(cx), "r"(cy), "r"(mbar) : "memory");
}
__device__ __forceinline__ void bulk_cp(uint32_t dst, const void* src, uint32_t bytes, uint32_t mbar) {
    asm volatile(
        "cp.async.bulk.shared::cta.global.mbarrier::complete_tx::bytes [%0], [%1], %2, [%3];"
        :: "r"(dst), "l"(src), "r"(bytes), "r"(mbar) : "memory");
}
__device__ __forceinline__ void ldm_x4(uint32_t* r, uint32_t addr) {
    asm volatile("ldmatrix.sync.aligned.m8n8.x4.shared.b16 {%0,%1,%2,%3}, [%4];"
        : "=r"(r[0]), "=r"(r[1]), "=r"(r[2]), "=r"(r[3]) : "r"(addr));
}
__device__ __forceinline__ void mma16816(float* c, const uint32_t* a, const uint32_t* b) {
    asm volatile("mma.sync.aligned.m16n8k16.row.col.f32.f16.f16.f32 "
        "{%0,%1,%2,%3}, {%4,%5,%6,%7}, {%8,%9}, {%0,%1,%2,%3};"
        : "+f"(c[0]), "+f"(c[1]), "+f"(c[2]), "+f"(c[3])
        : "r"(a[0]), "r"(a[1]), "r"(a[2]), "r"(a[3]), "r"(b[0]), "r"(b[1]));
}

// fp32 SW128 stage (64 rows x 128B) -> padded fp16 ping buffer (256 threads)
__device__ __forceinline__ void convert_chunk(const char* a32, char* a16, int tid) {
    const int crow = tid >> 2, q = tid & 3;
    const uint32_t rsw = (uint32_t)(crow & 7) << 4;
    const uint32_t b0 = (uint32_t)(crow * 128 + q * 32);
    float4 v0 = *reinterpret_cast<const float4*>(a32 + (b0 ^ rsw));
    float4 v1 = *reinterpret_cast<const float4*>(a32 + ((b0 + 16) ^ rsw));
    __half2 h0 = __floats2half2_rn(v0.x, v0.y);
    __half2 h1 = __floats2half2_rn(v0.z, v0.w);
    __half2 h2 = __floats2half2_rn(v1.x, v1.y);
    __half2 h3 = __floats2half2_rn(v1.z, v1.w);
    uint4 pk;
    pk.x = *reinterpret_cast<uint32_t*>(&h0);
    pk.y = *reinterpret_cast<uint32_t*>(&h1);
    pk.z = *reinterpret_cast<uint32_t*>(&h2);
    pk.w = *reinterpret_cast<uint32_t*>(&h3);
    *reinterpret_cast<uint4*>(a16 + crow * A16_ROWB + q * 16) = pk;
}

// ============================================================================
// Kernel 1 (prep): 128 CTAs x 512 threads, 128 nodes/CTA, single wave.
// ============================================================================
#define PREP_SMEM ((128 * DIM + 256 * 129) * 4 + 128 * 128 * 2)   // 230400

__global__ __launch_bounds__(512) void prep_kernel(const float* __restrict__ x,
                                                   const float* __restrict__ W,
                                                   const float* __restrict__ b) {
    extern __shared__ float sm1[];
    float*  xs  = sm1;                              // [128][128]
    float*  ws  = sm1 + 128 * DIM;                  // [256][129]
    __half* zsm = (__half*)(sm1 + 128 * DIM + 256 * 129);  // [128 o][128 node]
    const int tid = threadIdx.x;
    const int node0 = blockIdx.x * 128;

    const float4* xg = reinterpret_cast<const float4*>(x + (size_t)node0 * DIM);
    float4* xs4 = reinterpret_cast<float4*>(xs);
    #pragma unroll
    for (int i = tid; i < 128 * DIM / 4; i += 512) xs4[i] = xg[i];

    for (int idx = tid; idx < 256 * DIM; idx += 512) {
        int j = idx >> 7, k = idx & 127;
        float v = (j < DIM) ? W[j * 256 + DIM + k] : W[(j - DIM) * 256 + k];
        ws[j * 129 + k] = v;
    }
    __syncthreads();

    const int ng = tid >> 4;   // 0..31 -> nodes 4*ng .. 4*ng+3
    const int og = tid & 15;
    float acc[64];
    #pragma unroll
    for (int i = 0; i < 64; i++) acc[i] = 0.f;

    #pragma unroll 4
    for (int k = 0; k < DIM; ++k) {
        float xv[4];
        #pragma unroll
        for (int i = 0; i < 4; i++) xv[i] = xs[(4 * ng + i) * DIM + k];
        #pragma unroll
        for (int q = 0; q < 4; q++) {
            #pragma unroll
            for (int r = 0; r < 4; r++) {
                float wv = ws[(4 * og + 64 * q + r) * 129 + k];
                #pragma unroll
                for (int i = 0; i < 4; i++)
                    acc[i * 16 + 4 * q + r] = fmaf(xv[i], wv, acc[i * 16 + 4 * q + r]);
            }
        }
    }

    float4 bq0 = *reinterpret_cast<const float4*>(b + 4 * og);
    float4 bq1 = *reinterpret_cast<const float4*>(b + 4 * og + 64);

    #pragma unroll
    for (int i = 0; i < 4; i++) {
        int mloc = 4 * ng + i;
        #pragma unroll
        for (int q = 0; q < 2; q++)
            #pragma unroll
            for (int r = 0; r < 4; r++) {
                int j = 4 * og + 64 * q + r;
                zsm[j * 128 + mloc] = __float2half_rn(acc[i * 16 + 4 * q + r]);
            }
        float4 u0, u1;
        u0.x = acc[i*16+8] + bq0.x;  u0.y = acc[i*16+9] + bq0.y;
        u0.z = acc[i*16+10] + bq0.z; u0.w = acc[i*16+11] + bq0.w;
        u1.x = acc[i*16+12] + bq1.x; u1.y = acc[i*16+13] + bq1.y;
        u1.z = acc[i*16+14] + bq1.z; u1.w = acc[i*16+15] + bq1.w;
        *reinterpret_cast<float4*>(g_u + (size_t)(node0 + mloc) * DIM + 4 * og)      = u0;
        *reinterpret_cast<float4*>(g_u + (size_t)(node0 + mloc) * DIM + 4 * og + 64) = u1;
    }
    __syncthreads();

    {
        int o = tid >> 2, q = tid & 3;
        int c0 = blockIdx.x * 4;
        const uint4* src = reinterpret_cast<const uint4*>(zsm + o * 128 + q * 32);
        __half* dstp = g_zh + (size_t)(c0 + q) * BCHUNK_H + o * BROW_H;
        uint4* dst = reinterpret_cast<uint4*>(dstp);
        #pragma unroll
        for (int i = 0; i < 4; i++) dst[i] = src[i];
    }
}

// ============================================================================
// Kernel 2 (main): 512 CTAs x 256 threads, split-K x2, 2 CTAs/SM (103KB smem).
//   CTA: 64-row tile, K segment of 8192. Writes fp32 partials to g_part.
// ============================================================================
__global__ void __launch_bounds__(256, 2) gemm_kernel(
    const __grid_constant__ CUtensorMap tma_a) {
    extern __shared__ char smem[];
    const uint32_t sb = smem_u32(smem);
    const uint32_t MB = sb + SM_MBAR;

    const int tid  = threadIdx.x;
    const int lane = tid & 31;
    const int w    = tid >> 5;
    const int seg  = blockIdx.x & 1;
    const int m0g  = (blockIdx.x >> 1) * MTILE;
    const int c0   = seg * SEG_CHUNKS;
    const int m0w  = (w >> 2) * 32;     // warp tile 32x32
    const int n0w  = (w & 3) * 32;

    if (tid == 0) {
        #pragma unroll
        for (int s = 0; s < STAGES; ++s) mbar_init(MB + 8 * s, 1);
    }
    __syncthreads();

    if (tid == 0) {
        #pragma unroll
        for (int s = 0; s < STAGES; ++s) {
            mbar_expect_tx(MB + 8 * s, TXB);
            tma_2d(sb + SM_A32 + s * A32_BYTES, &tma_a, (c0 + s) * KC, m0g, MB + 8 * s);
            bulk_cp(sb + SM_B + s * BCHUNK_B, g_zh + (size_t)(c0 + s) * BCHUNK_H,
                    BCHUNK_B, MB + 8 * s);
        }
    }

    uint32_t aoff[2];
    #pragma unroll
    for (int mi = 0; mi < 2; ++mi)
        aoff[mi] = (uint32_t)((m0w + mi * 16 + (lane & 15)) * A16_ROWB + (lane >> 4) * 16);
    const int bg = lane >> 3;
    const uint32_t boff =
        (uint32_t)((n0w + ((bg >> 1) & 1) * 8 + (lane & 7)) * BROW_B + (bg & 1) * 16);

    float acc[2][4][4];
    #pragma unroll
    for (int i = 0; i < 2; i++)
        #pragma unroll
        for (int j = 0; j < 4; j++)
            #pragma unroll
            for (int k = 0; k < 4; k++) acc[i][j][k] = 0.f;

    // prologue: convert chunk 0 into ping[0]
    mbar_wait(MB + 8 * 0, 0);
    convert_chunk(smem + SM_A32 + 0 * A32_BYTES, smem + SM_A16 + 0 * A16_BYTES, tid);
    __syncthreads();

    int s = 0, ph = 0;
    #pragma unroll 1
    for (int it = 0; it < SEG_CHUNKS; ++it) {
        const uint32_t bst  = sb + SM_B + s * BCHUNK_B;
        const uint32_t a16b = sb + SM_A16 + (uint32_t)(it & 1) * A16_BYTES;

        // --- pre-barrier: all fragment loads for chunk it ---
        uint32_t bfr[2][2][4];
        #pragma unroll
        for (int nt2 = 0; nt2 < 2; ++nt2)
            #pragma unroll
            for (int ks = 0; ks < 2; ++ks)
                ldm_x4(bfr[nt2][ks], bst + boff + nt2 * 16 * BROW_B + ks * 32);

        uint32_t afr[2][2][4];
        #pragma unroll
        for (int ks = 0; ks < 2; ++ks)
            #pragma unroll
            for (int mi = 0; mi < 2; ++mi)
                ldm_x4(afr[ks][mi], a16b + aoff[mi] + ks * 32);

        // --- pre-barrier: convert chunk it+1 into the other ping buffer ---
        if (it + 1 < SEG_CHUNKS) {
            int sn  = (s + 1 == STAGES) ? 0 : s + 1;
            int phn = (s + 1 == STAGES) ? (ph ^ 1) : ph;
            mbar_wait(MB + 8 * sn, phn);
            convert_chunk(smem + SM_A32 + sn * A32_BYTES,
                          smem + SM_A16 + ((it + 1) & 1) * A16_BYTES, tid);
        }

        __syncthreads();

        // --- post-barrier: refill stage s ---
        if (tid == 0) {
            int nxt = it + STAGES;
            if (nxt < SEG_CHUNKS) {
                mbar_expect_tx(MB + 8 * s, TXB);
                tma_2d(sb + SM_A32 + s * A32_BYTES, &tma_a, (c0 + nxt) * KC, m0g, MB + 8 * s);
                bulk_cp(sb + SM_B + s * BCHUNK_B, g_zh + (size_t)(c0 + nxt) * BCHUNK_H,
                        BCHUNK_B, MB + 8 * s);
            }
        }

        // --- post-barrier: MMAs (register-only) ---
        #pragma unroll
        for (int ks = 0; ks < 2; ++ks)
            #pragma unroll
            for (int mi = 0; mi < 2; ++mi)
                #pragma unroll
                for (int nt = 0; nt < 4; ++nt)
                    mma16816(acc[mi][nt], afr[ks][mi], &bfr[nt >> 1][ks][(nt & 1) * 2]);

        if (++s == STAGES) { s = 0; ph ^= 1; }
    }

    // --- epilogue: store raw fp32 partials ---
    float* part = g_part + (size_t)seg * NNODES * DIM;
    #pragma unroll
    for (int mi = 0; mi < 2; ++mi) {
        int r = m0w + mi * 16 + (lane >> 2);
        #pragma unroll
        for (int nt = 0; nt < 4; ++nt) {
            int c = n0w + nt * 8 + 2 * (lane & 3);
            size_t i0 = (size_t)(m0g + r) * DIM + c;
            const float* a = acc[mi][nt];
            *reinterpret_cast<float2*>(part + i0)           = make_float2(a[0], a[1]);
            *reinterpret_cast<float2*>(part + i0 + 8 * DIM) = make_float2(a[2], a[3]);
        }
    }
}

// ============================================================================
// Kernel 3 (combine): out = ReLU(p0 + p1 + u), elementwise float4.
// ============================================================================
__global__ __launch_bounds__(256) void combine_kernel(float* __restrict__ out) {
    const size_t i = (size_t)blockIdx.x * 256 + threadIdx.x;   // float4 index
    const float4* p0 = reinterpret_cast<const float4*>(g_part);
    const float4* p1 = reinterpret_cast<const float4*>(g_part + (size_t)NNODES * DIM);
    const float4* uu = reinterpret_cast<const float4*>(g_u);
    float4 a = p0[i], b = p1[i], u = uu[i];
    float4 o;
    o.x = fmaxf(a.x + b.x + u.x, 0.f);
    o.y = fmaxf(a.y + b.y + u.y, 0.f);
    o.z = fmaxf(a.z + b.z + u.z, 0.f);
    o.w = fmaxf(a.w + b.w + u.w, 0.f);
    reinterpret_cast<float4*>(out)[i] = o;
}

// ============================================================================
// Host launch
// ============================================================================
typedef CUresult (*EncodeFn)(CUtensorMap*, CUtensorMapDataType, cuuint32_t, void*,
                             const cuuint64_t*, const cuuint64_t*, const cuuint32_t*,
                             const cuuint32_t*, CUtensorMapInterleave, CUtensorMapSwizzle,
                             CUtensorMapL2promotion, CUtensorMapFloatOOBfill);

extern "C" void kernel_launch(void* const* d_in, const int* in_sizes, int n_in,
                              void* d_out, int out_size) {
    const float *x = nullptr, *adj = nullptr, *W = nullptr, *b = nullptr;
    for (int i = 0; i < n_in; ++i) {
        switch (in_sizes[i]) {
            case NNODES * DIM: x = (const float*)d_in[i]; break;
            case 32768:        W = (const float*)d_in[i]; break;
            case 128:          b = (const float*)d_in[i]; break;
            default:           adj = (const float*)d_in[i]; break;
        }
    }
    float* out = (float*)d_out;

    void* fn = nullptr;
    cudaDriverEntryPointQueryResult qr;
#if CUDART_VERSION >= 12050
    cudaGetDriverEntryPointByVersion("cuTensorMapEncodeTiled", &fn, 12000,
                                     cudaEnableDefault, &qr);
#else
    cudaGetDriverEntryPoint("cuTensorMapEncodeTiled", &fn, cudaEnableDefault, &qr);
#endif
    if (!fn) return;
    EncodeFn encode = (EncodeFn)fn;

    CUtensorMap mapA;
    {
        cuuint64_t dims[2]   = {NNODES, NNODES};
        cuuint64_t stride[1] = {NNODES * 4ull};
        cuuint32_t box[2]    = {KC, MTILE};        // 128B x 64 rows, SW128
        cuuint32_t es[2]     = {1, 1};
        encode(&mapA, CU_TENSOR_MAP_DATA_TYPE_FLOAT32, 2, (void*)adj, dims, stride, box, es,
               CU_TENSOR_MAP_INTERLEAVE_NONE, CU_TENSOR_MAP_SWIZZLE_128B,
               CU_TENSOR_MAP_L2_PROMOTION_L2_128B, CU_TENSOR_MAP_FLOAT_OOB_FILL_NONE);
    }

    cudaFuncSetAttribute(prep_kernel, cudaFuncAttributeMaxDynamicSharedMemorySize, PREP_SMEM);
    cudaFuncSetAttribute(gemm_kernel, cudaFuncAttributeMaxDynamicSharedMemorySize, GEMM_SMEM);

    prep_kernel<<<NNODES / 128, 512, PREP_SMEM>>>(x, W, b);
    gemm_kernel<<<(NNODES / MTILE) * KSPLIT, 256, GEMM_SMEM>>>(mapA);
    combine_kernel<<<(NNODES * DIM / 4) / 256, 256>>>(out);
}

// round 8
// speedup vs baseline: 1.2898x; 1.0966x over previous
#include <cuda_runtime.h>
#include <cuda.h>
#include <cuda_fp16.h>
#include <cstdint>

// ---------------- problem constants ----------------
#define NNODES 16384
#define DIM    128
#define KC     32                          // K per chunk
#define CHUNKS (NNODES / KC)               // 512
#define KSPLIT 4
#define SEG_CHUNKS (CHUNKS / KSPLIT)       // 128 chunks per CTA
#define STAGES 5
#define MTILE  64

// B (zh) padded chunk layout: [chunk][o:128][40 halves] (32 data + 8 pad, 80B rows)
#define BROW_H   40
#define BROW_B   80
#define BCHUNK_H (DIM * BROW_H)            // 5120 halves = 10240 B
#define BCHUNK_B (BCHUNK_H * 2)

#define A32_BYTES (MTILE * KC * 4)         // 8192 B per stage (SW128 swizzled fp32)
#define A16_ROWB  80                       // padded fp16 A row stride
#define A16_BYTES (MTILE * A16_ROWB)       // 5120 B per ping buffer
#define TXB (A32_BYTES + BCHUNK_B)         // 18432

// smem layout (gemm kernel)
#define SM_MBAR 0
#define SM_A32  1024
#define SM_B    (1024 + STAGES * A32_BYTES)              // 41984
#define SM_A16  (SM_B + STAGES * BCHUNK_B)               // 93184
#define GEMM_SMEM (SM_A16 + 2 * A16_BYTES)               // 103424 -> 2 CTAs/SM

// scratch (__device__ globals: allocation-free rule)
__device__ __half g_zh[CHUNKS * BCHUNK_H];       // 5 MB, padded-chunk layout
__device__ float  g_u [NNODES * DIM];            // 8 MB: x@W1^T + b
__device__ float  g_part[KSPLIT * NNODES * DIM]; // 32 MB split-K partials

// ---------------- PTX helpers (compute_103-baseline only) ----------------
__device__ __forceinline__ uint32_t smem_u32(const void* p) {
    uint32_t a;
    asm("{ .reg .u64 t; cvta.to.shared.u64 t, %1; cvt.u32.u64 %0, t; }" : "=r"(a) : "l"(p));
    return a;
}
__device__ __forceinline__ void mbar_init(uint32_t mbar, uint32_t cnt) {
    asm volatile("mbarrier.init.shared.b64 [%0], %1;" :: "r"(mbar), "r"(cnt) : "memory");
}
__device__ __forceinline__ void mbar_expect_tx(uint32_t mbar, uint32_t bytes) {
    asm volatile("mbarrier.arrive.expect_tx.shared.b64 _, [%0], %1;" :: "r"(mbar), "r"(bytes) : "memory");
}
__device__ __forceinline__ void mbar_wait(uint32_t mbar, uint32_t parity) {
    asm volatile(
        "{\n\t.reg .pred P;\n\t"
        "W_%=:\n\t"
        "mbarrier.try_wait.parity.shared.b64 P, [%0], %1, 0x989680;\n\t"
        "@P bra D_%=;\n\t"
        "bra W_%=;\n\t"
        "D_%=:\n\t}"
        :: "r"(mbar), "r"(parity) : "memory");
}
__device__ __forceinline__ void tma_2d(uint32_t dst, const CUtensorMap* map,
                                       int cx, int cy, uint32_t mbar) {
    asm volatile(
        "cp.async.bulk.tensor.2d.shared::cta.global.tile.mbarrier::complete_tx::bytes "
        "[%0], [%1, {%2, %3}], [%4];"
        :: "r"(dst), "l"(map), "r"(cx), "r"(cy), "r"(mbar) : "memory");
}
__device__ __forceinline__ void bulk_cp(uint32_t dst, const void* src, uint32_t bytes, uint32_t mbar) {
    asm volatile(
        "cp.async.bulk.shared::cta.global.mbarrier::complete_tx::bytes [%0], [%1], %2, [%3];"
        :: "r"(dst), "l"(src), "r"(bytes), "r"(mbar) : "memory");
}
__device__ __forceinline__ void ldm_x4(uint32_t* r, uint32_t addr) {
    asm volatile("ldmatrix.sync.aligned.m8n8.x4.shared.b16 {%0,%1,%2,%3}, [%4];"
        : "=r"(r[0]), "=r"(r[1]), "=r"(r[2]), "=r"(r[3]) : "r"(addr));
}
__device__ __forceinline__ void mma16816(float* c, const uint32_t* a, const uint32_t* b) {
    asm volatile("mma.sync.aligned.m16n8k16.row.col.f32.f16.f16.f32 "
        "{%0,%1,%2,%3}, {%4,%5,%6,%7}, {%8,%9}, {%0,%1,%2,%3};"
        : "+f"(c[0]), "+f"(c[1]), "+f"(c[2]), "+f"(c[3])
        : "r"(a[0]), "r"(a[1]), "r"(a[2]), "r"(a[3]), "r"(b[0]), "r"(b[1]));
}

// fp32 SW128 stage (64 rows x 128B) -> padded fp16 ping buffer (256 threads)
__device__ __forceinline__ void convert_chunk(const char* a32, char* a16, int tid) {
    const int crow = tid >> 2, q = tid & 3;
    const uint32_t rsw = (uint32_t)(crow & 7) << 4;
    const uint32_t b0 = (uint32_t)(crow * 128 + q * 32);
    float4 v0 = *reinterpret_cast<const float4*>(a32 + (b0 ^ rsw));
    float4 v1 = *reinterpret_cast<const float4*>(a32 + ((b0 + 16) ^ rsw));
    __half2 h0 = __floats2half2_rn(v0.x, v0.y);
    __half2 h1 = __floats2half2_rn(v0.z, v0.w);
    __half2 h2 = __floats2half2_rn(v1.x, v1.y);
    __half2 h3 = __floats2half2_rn(v1.z, v1.w);
    uint4 pk;
    pk.x = *reinterpret_cast<uint32_t*>(&h0);
    pk.y = *reinterpret_cast<uint32_t*>(&h1);
    pk.z = *reinterpret_cast<uint32_t*>(&h2);
    pk.w = *reinterpret_cast<uint32_t*>(&h3);
    *reinterpret_cast<uint4*>(a16 + crow * A16_ROWB + q * 16) = pk;
}

// ============================================================================
// Kernel 1 (prep, tensor-core): 256 CTAs x 256 threads, 64 nodes/CTA.
//   xh = fp16(x tile) [64 x 128], wh = fp16(W reordered) [256 x 128]
//   acc = xh @ wh^T  (m16n8k16, fp32 accum)
//   cols 0..127  -> z  -> fp16 -> g_zh (padded chunk layout, via smem staging)
//   cols 128..255-> u  -> + bias -> g_u fp32
// ============================================================================
#define PT_ROWB 272                        // fp16 K-major row stride (256B data + 16 pad)
#define PT_XH   1024
#define PT_WH   (PT_XH + 64 * PT_ROWB)     // 18432
#define PT_ZS   (PT_WH + 256 * PT_ROWB)    // 88064
#define ZS_STRH 72                         // zsm row stride in halves (144B)
#define PREP_SMEM (PT_ZS + 128 * ZS_STRH * 2)   // 106496

__global__ void __launch_bounds__(256, 2) prep_kernel(const float* __restrict__ x,
                                                      const float* __restrict__ W,
                                                      const float* __restrict__ b) {
    extern __shared__ char smem[];
    const uint32_t sb = smem_u32(smem);
    const int tid  = threadIdx.x;
    const int lane = tid & 31;
    const int w    = tid >> 5;
    const int node0 = blockIdx.x * 64;

    // --- load + convert x tile [64][128] fp32 -> xh fp16 (K-major, padded) ---
    #pragma unroll
    for (int i = 0; i < 8; ++i) {
        int idx = tid + i * 256;               // 2048 float4s
        int row = idx >> 5, c4 = idx & 31;
        float4 v = reinterpret_cast<const float4*>(x + (size_t)(node0 + row) * DIM)[c4];
        __half2 h0 = __floats2half2_rn(v.x, v.y);
        __half2 h1 = __floats2half2_rn(v.z, v.w);
        uint2 pk;
        pk.x = *reinterpret_cast<uint32_t*>(&h0);
        pk.y = *reinterpret_cast<uint32_t*>(&h1);
        *reinterpret_cast<uint2*>(smem + PT_XH + row * PT_ROWB + c4 * 8) = pk;
    }
    // --- load + convert W: rows 0..127 = W[j][128+k] (z), 128..255 = W[j-128][k] (u)
    #pragma unroll
    for (int i = 0; i < 32; ++i) {
        int idx = tid + i * 256;               // 8192 float4s
        int j = idx >> 5, c4 = idx & 31;
        const float* src = (j < DIM) ? (W + j * 256 + DIM) : (W + (j - DIM) * 256);
        float4 v = reinterpret_cast<const float4*>(src)[c4];
        __half2 h0 = __floats2half2_rn(v.x, v.y);
        __half2 h1 = __floats2half2_rn(v.z, v.w);
        uint2 pk;
        pk.x = *reinterpret_cast<uint32_t*>(&h0);
        pk.y = *reinterpret_cast<uint32_t*>(&h1);
        *reinterpret_cast<uint2*>(smem + PT_WH + j * PT_ROWB + c4 * 8) = pk;
    }
    __syncthreads();

    // --- warp tiles: m0w in {0,32}, n0w in {0,64,128,192} ---
    const int m0w = (w >> 2) * 32;
    const int n0w = (w & 3) * 64;
    uint32_t aoff[2];
    #pragma unroll
    for (int mi = 0; mi < 2; ++mi)
        aoff[mi] = (uint32_t)(PT_XH + (m0w + mi * 16 + (lane & 15)) * PT_ROWB + (lane >> 4) * 16);
    const int bg = lane >> 3;
    const uint32_t boff =
        (uint32_t)(PT_WH + (n0w + ((bg >> 1) & 1) * 8 + (lane & 7)) * PT_ROWB + (bg & 1) * 16);

    float acc[2][8][4];
    #pragma unroll
    for (int i = 0; i < 2; i++)
        #pragma unroll
        for (int j = 0; j < 8; j++)
            #pragma unroll
            for (int k = 0; k < 4; k++) acc[i][j][k] = 0.f;

    #pragma unroll
    for (int ks = 0; ks < 8; ++ks) {
        uint32_t afr[2][4];
        #pragma unroll
        for (int mi = 0; mi < 2; ++mi)
            ldm_x4(afr[mi], sb + aoff[mi] + ks * 32);
        uint32_t bfr[4][4];
        #pragma unroll
        for (int nt2 = 0; nt2 < 4; ++nt2)
            ldm_x4(bfr[nt2], sb + boff + nt2 * 16 * PT_ROWB + ks * 32);
        #pragma unroll
        for (int mi = 0; mi < 2; ++mi)
            #pragma unroll
            for (int nt = 0; nt < 8; ++nt)
                mma16816(acc[mi][nt], afr[mi], &bfr[nt >> 1][(nt & 1) * 2]);
    }

    // --- epilogue ---
    __half* zs = reinterpret_cast<__half*>(smem + PT_ZS);
    if (n0w < 128) {
        // z warps: stage fp16 into zs[o][node]
        #pragma unroll
        for (int mi = 0; mi < 2; ++mi) {
            int r = m0w + mi * 16 + (lane >> 2);
            #pragma unroll
            for (int nt = 0; nt < 8; ++nt) {
                int n = n0w + nt * 8 + 2 * (lane & 3);
                const float* a = acc[mi][nt];
                zs[n * ZS_STRH + r]           = __float2half_rn(a[0]);
                zs[(n + 1) * ZS_STRH + r]     = __float2half_rn(a[1]);
                zs[n * ZS_STRH + r + 8]       = __float2half_rn(a[2]);
                zs[(n + 1) * ZS_STRH + r + 8] = __float2half_rn(a[3]);
            }
        }
    } else {
        // u warps: + bias, direct fp32 global
        #pragma unroll
        for (int mi = 0; mi < 2; ++mi) {
            int r = m0w + mi * 16 + (lane >> 2);
            #pragma unroll
            for (int nt = 0; nt < 8; ++nt) {
                int o = n0w - 128 + nt * 8 + 2 * (lane & 3);
                float2 bo = *reinterpret_cast<const float2*>(b + o);
                const float* a = acc[mi][nt];
                *reinterpret_cast<float2*>(g_u + (size_t)(node0 + r) * DIM + o) =
                    make_float2(a[0] + bo.x, a[1] + bo.y);
                *reinterpret_cast<float2*>(g_u + (size_t)(node0 + r + 8) * DIM + o) =
                    make_float2(a[2] + bo.x, a[3] + bo.y);
            }
        }
    }
    __syncthreads();

    // coalesced z write-out: thread -> (o = tid>>1, q = tid&1 covering 32 nodes)
    {
        int o = tid >> 1, q = tid & 1;
        const uint4* src = reinterpret_cast<const uint4*>(smem + PT_ZS + o * (ZS_STRH * 2) + q * 64);
        uint4* dst = reinterpret_cast<uint4*>(g_zh + (size_t)(blockIdx.x * 2 + q) * BCHUNK_H + o * BROW_H);
        #pragma unroll
        for (int i = 0; i < 4; i++) dst[i] = src[i];
    }
}

// ============================================================================
// Kernel 2 (main): 1024 CTAs x 256 threads, split-K x4, 2 CTAs/SM (103KB smem).
//   CTA: 64-row tile, K segment of 4096. Writes fp32 partials to g_part.
// ============================================================================
__global__ void __launch_bounds__(256, 2) gemm_kernel(
    const __grid_constant__ CUtensorMap tma_a) {
    extern __shared__ char smem[];
    const uint32_t sb = smem_u32(smem);
    const uint32_t MB = sb + SM_MBAR;

    const int tid  = threadIdx.x;
    const int lane = tid & 31;
    const int w    = tid >> 5;
    const int seg  = blockIdx.x & (KSPLIT - 1);
    const int m0g  = (blockIdx.x >> 2) * MTILE;
    const int c0   = seg * SEG_CHUNKS;
    const int m0w  = (w >> 2) * 32;     // warp tile 32x32
    const int n0w  = (w & 3) * 32;

    if (tid == 0) {
        #pragma unroll
        for (int s = 0; s < STAGES; ++s) mbar_init(MB + 8 * s, 1);
    }
    __syncthreads();

    if (tid == 0) {
        #pragma unroll
        for (int s = 0; s < STAGES; ++s) {
            mbar_expect_tx(MB + 8 * s, TXB);
            tma_2d(sb + SM_A32 + s * A32_BYTES, &tma_a, (c0 + s) * KC, m0g, MB + 8 * s);
            bulk_cp(sb + SM_B + s * BCHUNK_B, g_zh + (size_t)(c0 + s) * BCHUNK_H,
                    BCHUNK_B, MB + 8 * s);
        }
    }

    uint32_t aoff[2];
    #pragma unroll
    for (int mi = 0; mi < 2; ++mi)
        aoff[mi] = (uint32_t)((m0w + mi * 16 + (lane & 15)) * A16_ROWB + (lane >> 4) * 16);
    const int bg = lane >> 3;
    const uint32_t boff =
        (uint32_t)((n0w + ((bg >> 1) & 1) * 8 + (lane & 7)) * BROW_B + (bg & 1) * 16);

    float acc[2][4][4];
    #pragma unroll
    for (int i = 0; i < 2; i++)
        #pragma unroll
        for (int j = 0; j < 4; j++)
            #pragma unroll
            for (int k = 0; k < 4; k++) acc[i][j][k] = 0.f;

    // prologue: convert chunk 0 into ping[0]
    mbar_wait(MB + 8 * 0, 0);
    convert_chunk(smem + SM_A32 + 0 * A32_BYTES, smem + SM_A16 + 0 * A16_BYTES, tid);
    __syncthreads();

    int s = 0, ph = 0;
    #pragma unroll 1
    for (int it = 0; it < SEG_CHUNKS; ++it) {
        const uint32_t bst  = sb + SM_B + s * BCHUNK_B;
        const uint32_t a16b = sb + SM_A16 + (uint32_t)(it & 1) * A16_BYTES;

        // --- pre-barrier: all fragment loads for chunk it ---
        uint32_t bfr[2][2][4];
        #pragma unroll
        for (int nt2 = 0; nt2 < 2; ++nt2)
            #pragma unroll
            for (int ks = 0; ks < 2; ++ks)
                ldm_x4(bfr[nt2][ks], bst + boff + nt2 * 16 * BROW_B + ks * 32);

        uint32_t afr[2][2][4];
        #pragma unroll
        for (int ks = 0; ks < 2; ++ks)
            #pragma unroll
            for (int mi = 0; mi < 2; ++mi)
                ldm_x4(afr[ks][mi], a16b + aoff[mi] + ks * 32);

        // --- pre-barrier: convert chunk it+1 into the other ping buffer ---
        if (it + 1 < SEG_CHUNKS) {
            int sn  = (s + 1 == STAGES) ? 0 : s + 1;
            int phn = (s + 1 == STAGES) ? (ph ^ 1) : ph;
            mbar_wait(MB + 8 * sn, phn);
            convert_chunk(smem + SM_A32 + sn * A32_BYTES,
                          smem + SM_A16 + ((it + 1) & 1) * A16_BYTES, tid);
        }

        __syncthreads();

        // --- post-barrier: refill stage s ---
        if (tid == 0) {
            int nxt = it + STAGES;
            if (nxt < SEG_CHUNKS) {
                mbar_expect_tx(MB + 8 * s, TXB);
                tma_2d(sb + SM_A32 + s * A32_BYTES, &tma_a, (c0 + nxt) * KC, m0g, MB + 8 * s);
                bulk_cp(sb + SM_B + s * BCHUNK_B, g_zh + (size_t)(c0 + nxt) * BCHUNK_H,
                        BCHUNK_B, MB + 8 * s);
            }
        }

        // --- post-barrier: MMAs (register-only) ---
        #pragma unroll
        for (int ks = 0; ks < 2; ++ks)
            #pragma unroll
            for (int mi = 0; mi < 2; ++mi)
                #pragma unroll
                for (int nt = 0; nt < 4; ++nt)
                    mma16816(acc[mi][nt], afr[ks][mi], &bfr[nt >> 1][ks][(nt & 1) * 2]);

        if (++s == STAGES) { s = 0; ph ^= 1; }
    }

    // --- epilogue: store raw fp32 partials ---
    float* part = g_part + (size_t)seg * NNODES * DIM;
    #pragma unroll
    for (int mi = 0; mi < 2; ++mi) {
        int r = m0w + mi * 16 + (lane >> 2);
        #pragma unroll
        for (int nt = 0; nt < 4; ++nt) {
            int c = n0w + nt * 8 + 2 * (lane & 3);
            size_t i0 = (size_t)(m0g + r) * DIM + c;
            const float* a = acc[mi][nt];
            *reinterpret_cast<float2*>(part + i0)           = make_float2(a[0], a[1]);
            *reinterpret_cast<float2*>(part + i0 + 8 * DIM) = make_float2(a[2], a[3]);
        }
    }
}

// ============================================================================
// Kernel 3 (combine): out = ReLU(p0+p1+p2+p3+u), elementwise float4.
// ============================================================================
__global__ __launch_bounds__(256) void combine_kernel(float* __restrict__ out) {
    const size_t i = (size_t)blockIdx.x * 256 + threadIdx.x;   // float4 index
    const size_t stride4 = (size_t)NNODES * DIM / 4;
    const float4* p = reinterpret_cast<const float4*>(g_part);
    const float4* uu = reinterpret_cast<const float4*>(g_u);
    float4 a0 = p[i], a1 = p[i + stride4], a2 = p[i + 2 * stride4], a3 = p[i + 3 * stride4];
    float4 u = uu[i];
    float4 o;
    o.x = fmaxf((a0.x + a1.x) + (a2.x + a3.x) + u.x, 0.f);
    o.y = fmaxf((a0.y + a1.y) + (a2.y + a3.y) + u.y, 0.f);
    o.z = fmaxf((a0.z + a1.z) + (a2.z + a3.z) + u.z, 0.f);
    o.w = fmaxf((a0.w + a1.w) + (a2.w + a3.w) + u.w, 0.f);
    reinterpret_cast<float4*>(out)[i] = o;
}

// ============================================================================
// Host launch
// ============================================================================
typedef CUresult (*EncodeFn)(CUtensorMap*, CUtensorMapDataType, cuuint32_t, void*,
                             const cuuint64_t*, const cuuint64_t*, const cuuint32_t*,
                             const cuuint32_t*, CUtensorMapInterleave, CUtensorMapSwizzle,
                             CUtensorMapL2promotion, CUtensorMapFloatOOBfill);

extern "C" void kernel_launch(void* const* d_in, const int* in_sizes, int n_in,
                              void* d_out, int out_size) {
    const float *x = nullptr, *adj = nullptr, *W = nullptr, *b = nullptr;
    for (int i = 0; i < n_in; ++i) {
        switch (in_sizes[i]) {
            case NNODES * DIM: x = (const float*)d_in[i]; break;
            case 32768:        W = (const float*)d_in[i]; break;
            case 128:          b = (const float*)d_in[i]; break;
            default:           adj = (const float*)d_in[i]; break;
        }
    }
    float* out = (float*)d_out;

    void* fn = nullptr;
    cudaDriverEntryPointQueryResult qr;
#if CUDART_VERSION >= 12050
    cudaGetDriverEntryPointByVersion("cuTensorMapEncodeTiled", &fn, 12000,
                                     cudaEnableDefault, &qr);
#else
    cudaGetDriverEntryPoint("cuTensorMapEncodeTiled", &fn, cudaEnableDefault, &qr);
#endif
    if (!fn) return;
    EncodeFn encode = (EncodeFn)fn;

    CUtensorMap mapA;
    {
        cuuint64_t dims[2]   = {NNODES, NNODES};
        cuuint64_t stride[1] = {NNODES * 4ull};
        cuuint32_t box[2]    = {KC, MTILE};        // 128B x 64 rows, SW128
        cuuint32_t es[2]     = {1, 1};
        encode(&mapA, CU_TENSOR_MAP_DATA_TYPE_FLOAT32, 2, (void*)adj, dims, stride, box, es,
               CU_TENSOR_MAP_INTERLEAVE_NONE, CU_TENSOR_MAP_SWIZZLE_128B,
               CU_TENSOR_MAP_L2_PROMOTION_L2_128B, CU_TENSOR_MAP_FLOAT_OOB_FILL_NONE);
    }

    cudaFuncSetAttribute(prep_kernel, cudaFuncAttributeMaxDynamicSharedMemorySize, PREP_SMEM);
    cudaFuncSetAttribute(gemm_kernel, cudaFuncAttributeMaxDynamicSharedMemorySize, GEMM_SMEM);

    prep_kernel<<<NNODES / 64, 256, PREP_SMEM>>>(x, W, b);
    gemm_kernel<<<(NNODES / MTILE) * KSPLIT, 256, GEMM_SMEM>>>(mapA);
    combine_kernel<<<(NNODES * DIM / 4) / 256, 256>>>(out);
}

// round 9
// speedup vs baseline: 1.3686x; 1.0611x over previous
#include <cuda_runtime.h>
#include <cuda.h>
#include <cuda_fp16.h>
#include <cstdint>

// ---------------- problem constants ----------------
#define NNODES 16384
#define DIM    128
#define KC     32                          // K per chunk
#define CHUNKS (NNODES / KC)               // 512
#define KSPLIT 4
#define SEG_CHUNKS (CHUNKS / KSPLIT)       // 128 chunks per CTA
#define STAGES 3
#define MTILE  128                         // CTA rows (amortizes B/conv crossbar traffic)

// B (zh) padded chunk layout: [chunk][o:128][40 halves] (32 data + 8 pad, 80B rows)
#define BROW_H   40
#define BROW_B   80
#define BCHUNK_H (DIM * BROW_H)            // 5120 halves = 10240 B
#define BCHUNK_B (BCHUNK_H * 2)

#define A32_BYTES (MTILE * KC * 4)         // 16384 B per stage (SW128 swizzled fp32)
#define A16_ROWB  80                       // padded fp16 A row stride
#define A16_BYTES (MTILE * A16_ROWB)       // 10240 B per ping buffer
#define TXB (A32_BYTES + BCHUNK_B)         // 26624

// smem layout (gemm kernel)
#define SM_MBAR 0
#define SM_A32  1024
#define SM_B    (1024 + STAGES * A32_BYTES)              // 50176
#define SM_A16  (SM_B + STAGES * BCHUNK_B)               // 80896
#define GEMM_SMEM (SM_A16 + 2 * A16_BYTES)               // 101376 -> 2 CTAs/SM

// scratch (__device__ globals: allocation-free rule)
__device__ __half g_zh[CHUNKS * BCHUNK_H];       // 5 MB, padded-chunk layout
__device__ float  g_u [NNODES * DIM];            // 8 MB: x@W1^T + b
__device__ float  g_part[KSPLIT * NNODES * DIM]; // 32 MB split-K partials

// ---------------- PTX helpers (compute_103-baseline only) ----------------
__device__ __forceinline__ uint32_t smem_u32(const void* p) {
    uint32_t a;
    asm("{ .reg .u64 t; cvta.to.shared.u64 t, %1; cvt.u32.u64 %0, t; }" : "=r"(a) : "l"(p));
    return a;
}
__device__ __forceinline__ void mbar_init(uint32_t mbar, uint32_t cnt) {
    asm volatile("mbarrier.init.shared.b64 [%0], %1;" :: "r"(mbar), "r"(cnt) : "memory");
}
__device__ __forceinline__ void mbar_expect_tx(uint32_t mbar, uint32_t bytes) {
    asm volatile("mbarrier.arrive.expect_tx.shared.b64 _, [%0], %1;" :: "r"(mbar), "r"(bytes) : "memory");
}
__device__ __forceinline__ void mbar_wait(uint32_t mbar, uint32_t parity) {
    asm volatile(
        "{\n\t.reg .pred P;\n\t"
        "W_%=:\n\t"
        "mbarrier.try_wait.parity.shared.b64 P, [%0], %1, 0x989680;\n\t"
        "@P bra D_%=;\n\t"
        "bra W_%=;\n\t"
        "D_%=:\n\t}"
        :: "r"(mbar), "r"(parity) : "memory");
}
__device__ __forceinline__ void tma_2d(uint32_t dst, const CUtensorMap* map,
                                       int cx, int cy, uint32_t mbar) {
    asm volatile(
        "cp.async.bulk.tensor.2d.shared::cta.global.tile.mbarrier::complete_tx::bytes "
        "[%0], [%1, {%2, %3}], [%4];"
        :: "r"(dst), "l"(map), "r"(cx), "r"(cy), "r"(mbar) : "memory");
}
__device__ __forceinline__ void bulk_cp(uint32_t dst, const void* src, uint32_t bytes, uint32_t mbar) {
    asm volatile(
        "cp.async.bulk.shared::cta.global.mbarrier::complete_tx::bytes [%0], [%1], %2, [%3];"
        :: "r"(dst), "l"(src), "r"(bytes), "r"(mbar) : "memory");
}
__device__ __forceinline__ void ldm_x4(uint32_t* r, uint32_t addr) {
    asm volatile("ldmatrix.sync.aligned.m8n8.x4.shared.b16 {%0,%1,%2,%3}, [%4];"
        : "=r"(r[0]), "=r"(r[1]), "=r"(r[2]), "=r"(r[3]) : "r"(addr));
}
__device__ __forceinline__ void mma16816(float* c, const uint32_t* a, const uint32_t* b) {
    asm volatile("mma.sync.aligned.m16n8k16.row.col.f32.f16.f16.f32 "
        "{%0,%1,%2,%3}, {%4,%5,%6,%7}, {%8,%9}, {%0,%1,%2,%3};"
        : "+f"(c[0]), "+f"(c[1]), "+f"(c[2]), "+f"(c[3])
        : "r"(a[0]), "r"(a[1]), "r"(a[2]), "r"(a[3]), "r"(b[0]), "r"(b[1]));
}

// fp32 SW128 stage (128 rows x 128B) -> padded fp16 ping buffer (256 threads)
__device__ __forceinline__ void convert_chunk(const char* a32, char* a16, int tid) {
    const int crow = tid >> 1, chalf = tid & 1;
    const uint32_t rsw = (uint32_t)(crow & 7) << 4;
    char* dst = a16 + crow * A16_ROWB + chalf * 32;
    #pragma unroll
    for (int jp = 0; jp < 2; ++jp) {
        uint32_t b0 = (uint32_t)(crow * 128 + chalf * 64 + jp * 32);
        float4 v0 = *reinterpret_cast<const float4*>(a32 + (b0 ^ rsw));
        float4 v1 = *reinterpret_cast<const float4*>(a32 + ((b0 + 16) ^ rsw));
        __half2 h0 = __floats2half2_rn(v0.x, v0.y);
        __half2 h1 = __floats2half2_rn(v0.z, v0.w);
        __half2 h2 = __floats2half2_rn(v1.x, v1.y);
        __half2 h3 = __floats2half2_rn(v1.z, v1.w);
        uint4 pk;
        pk.x = *reinterpret_cast<uint32_t*>(&h0);
        pk.y = *reinterpret_cast<uint32_t*>(&h1);
        pk.z = *reinterpret_cast<uint32_t*>(&h2);
        pk.w = *reinterpret_cast<uint32_t*>(&h3);
        *reinterpret_cast<uint4*>(dst + jp * 16) = pk;
    }
}

// ============================================================================
// Kernel 1 (prep, tensor-core): 256 CTAs x 256 threads, 64 nodes/CTA.
// ============================================================================
#define PT_ROWB 272
#define PT_XH   1024
#define PT_WH   (PT_XH + 64 * PT_ROWB)     // 18432
#define PT_ZS   (PT_WH + 256 * PT_ROWB)    // 88064
#define ZS_STRH 72
#define PREP_SMEM (PT_ZS + 128 * ZS_STRH * 2)   // 106496

__global__ void __launch_bounds__(256, 2) prep_kernel(const float* __restrict__ x,
                                                      const float* __restrict__ W,
                                                      const float* __restrict__ b) {
    extern __shared__ char smem[];
    const uint32_t sb = smem_u32(smem);
    const int tid  = threadIdx.x;
    const int lane = tid & 31;
    const int w    = tid >> 5;
    const int node0 = blockIdx.x * 64;

    #pragma unroll
    for (int i = 0; i < 8; ++i) {
        int idx = tid + i * 256;
        int row = idx >> 5, c4 = idx & 31;
        float4 v = reinterpret_cast<const float4*>(x + (size_t)(node0 + row) * DIM)[c4];
        __half2 h0 = __floats2half2_rn(v.x, v.y);
        __half2 h1 = __floats2half2_rn(v.z, v.w);
        uint2 pk;
        pk.x = *reinterpret_cast<uint32_t*>(&h0);
        pk.y = *reinterpret_cast<uint32_t*>(&h1);
        *reinterpret_cast<uint2*>(smem + PT_XH + row * PT_ROWB + c4 * 8) = pk;
    }
    #pragma unroll
    for (int i = 0; i < 32; ++i) {
        int idx = tid + i * 256;
        int j = idx >> 5, c4 = idx & 31;
        const float* src = (j < DIM) ? (W + j * 256 + DIM) : (W + (j - DIM) * 256);
        float4 v = reinterpret_cast<const float4*>(src)[c4];
        __half2 h0 = __floats2half2_rn(v.x, v.y);
        __half2 h1 = __floats2half2_rn(v.z, v.w);
        uint2 pk;
        pk.x = *reinterpret_cast<uint32_t*>(&h0);
        pk.y = *reinterpret_cast<uint32_t*>(&h1);
        *reinterpret_cast<uint2*>(smem + PT_WH + j * PT_ROWB + c4 * 8) = pk;
    }
    __syncthreads();

    const int m0w = (w >> 2) * 32;
    const int n0w = (w & 3) * 64;
    uint32_t aoff[2];
    #pragma unroll
    for (int mi = 0; mi < 2; ++mi)
        aoff[mi] = (uint32_t)(PT_XH + (m0w + mi * 16 + (lane & 15)) * PT_ROWB + (lane >> 4) * 16);
    const int bg = lane >> 3;
    const uint32_t boff =
        (uint32_t)(PT_WH + (n0w + ((bg >> 1) & 1) * 8 + (lane & 7)) * PT_ROWB + (bg & 1) * 16);

    float acc[2][8][4];
    #pragma unroll
    for (int i = 0; i < 2; i++)
        #pragma unroll
        for (int j = 0; j < 8; j++)
            #pragma unroll
            for (int k = 0; k < 4; k++) acc[i][j][k] = 0.f;

    #pragma unroll
    for (int ks = 0; ks < 8; ++ks) {
        uint32_t afr[2][4];
        #pragma unroll
        for (int mi = 0; mi < 2; ++mi)
            ldm_x4(afr[mi], sb + aoff[mi] + ks * 32);
        uint32_t bfr[4][4];
        #pragma unroll
        for (int nt2 = 0; nt2 < 4; ++nt2)
            ldm_x4(bfr[nt2], sb + boff + nt2 * 16 * PT_ROWB + ks * 32);
        #pragma unroll
        for (int mi = 0; mi < 2; ++mi)
            #pragma unroll
            for (int nt = 0; nt < 8; ++nt)
                mma16816(acc[mi][nt], afr[mi], &bfr[nt >> 1][(nt & 1) * 2]);
    }

    __half* zs = reinterpret_cast<__half*>(smem + PT_ZS);
    if (n0w < 128) {
        #pragma unroll
        for (int mi = 0; mi < 2; ++mi) {
            int r = m0w + mi * 16 + (lane >> 2);
            #pragma unroll
            for (int nt = 0; nt < 8; ++nt) {
                int n = n0w + nt * 8 + 2 * (lane & 3);
                const float* a = acc[mi][nt];
                zs[n * ZS_STRH + r]           = __float2half_rn(a[0]);
                zs[(n + 1) * ZS_STRH + r]     = __float2half_rn(a[1]);
                zs[n * ZS_STRH + r + 8]       = __float2half_rn(a[2]);
                zs[(n + 1) * ZS_STRH + r + 8] = __float2half_rn(a[3]);
            }
        }
    } else {
        #pragma unroll
        for (int mi = 0; mi < 2; ++mi) {
            int r = m0w + mi * 16 + (lane >> 2);
            #pragma unroll
            for (int nt = 0; nt < 8; ++nt) {
                int o = n0w - 128 + nt * 8 + 2 * (lane & 3);
                float2 bo = *reinterpret_cast<const float2*>(b + o);
                const float* a = acc[mi][nt];
                *reinterpret_cast<float2*>(g_u + (size_t)(node0 + r) * DIM + o) =
                    make_float2(a[0] + bo.x, a[1] + bo.y);
                *reinterpret_cast<float2*>(g_u + (size_t)(node0 + r + 8) * DIM + o) =
                    make_float2(a[2] + bo.x, a[3] + bo.y);
            }
        }
    }
    __syncthreads();

    {
        int o = tid >> 1, q = tid & 1;
        const uint4* src = reinterpret_cast<const uint4*>(smem + PT_ZS + o * (ZS_STRH * 2) + q * 64);
        uint4* dst = reinterpret_cast<uint4*>(g_zh + (size_t)(blockIdx.x * 2 + q) * BCHUNK_H + o * BROW_H);
        #pragma unroll
        for (int i = 0; i < 4; i++) dst[i] = src[i];
    }
}

// ============================================================================
// Kernel 2 (main): 512 CTAs x 256 threads, MTILE=128, split-K x4, 2 CTAs/SM.
//   Warp grid 2(M) x 4(N), warp tile 64x32 (mi=4). ks=0 MMAs pre-barrier to
//   keep register peak under the 128/thread cap.
// ============================================================================
__global__ void __launch_bounds__(256, 2) gemm_kernel(
    const __grid_constant__ CUtensorMap tma_a) {
    extern __shared__ char smem[];
    const uint32_t sb = smem_u32(smem);
    const uint32_t MB = sb + SM_MBAR;

    const int tid  = threadIdx.x;
    const int lane = tid & 31;
    const int w    = tid >> 5;
    const int seg  = blockIdx.x & (KSPLIT - 1);
    const int m0g  = (blockIdx.x >> 2) * MTILE;
    const int c0   = seg * SEG_CHUNKS;
    const int m0w  = (w >> 2) * 64;     // warp tile 64x32
    const int n0w  = (w & 3) * 32;

    if (tid == 0) {
        #pragma unroll
        for (int s = 0; s < STAGES; ++s) mbar_init(MB + 8 * s, 1);
    }
    __syncthreads();

    if (tid == 0) {
        #pragma unroll
        for (int s = 0; s < STAGES; ++s) {
            mbar_expect_tx(MB + 8 * s, TXB);
            tma_2d(sb + SM_A32 + s * A32_BYTES, &tma_a, (c0 + s) * KC, m0g, MB + 8 * s);
            bulk_cp(sb + SM_B + s * BCHUNK_B, g_zh + (size_t)(c0 + s) * BCHUNK_H,
                    BCHUNK_B, MB + 8 * s);
        }
    }

    uint32_t aoff[4];
    #pragma unroll
    for (int mi = 0; mi < 4; ++mi)
        aoff[mi] = (uint32_t)((m0w + mi * 16 + (lane & 15)) * A16_ROWB + (lane >> 4) * 16);
    const int bg = lane >> 3;
    const uint32_t boff =
        (uint32_t)((n0w + ((bg >> 1) & 1) * 8 + (lane & 7)) * BROW_B + (bg & 1) * 16);

    float acc[4][4][4];
    #pragma unroll
    for (int i = 0; i < 4; i++)
        #pragma unroll
        for (int j = 0; j < 4; j++)
            #pragma unroll
            for (int k = 0; k < 4; k++) acc[i][j][k] = 0.f;

    // prologue: convert chunk 0 into ping[0]
    mbar_wait(MB + 8 * 0, 0);
    convert_chunk(smem + SM_A32 + 0 * A32_BYTES, smem + SM_A16 + 0 * A16_BYTES, tid);
    __syncthreads();

    int s = 0, ph = 0;
    #pragma unroll 1
    for (int it = 0; it < SEG_CHUNKS; ++it) {
        const uint32_t bst  = sb + SM_B + s * BCHUNK_B;
        const uint32_t a16b = sb + SM_A16 + (uint32_t)(it & 1) * A16_BYTES;

        // --- pre-barrier: B fragments (both ks) ---
        uint32_t bfr[2][2][4];
        #pragma unroll
        for (int nt2 = 0; nt2 < 2; ++nt2)
            #pragma unroll
            for (int ks = 0; ks < 2; ++ks)
                ldm_x4(bfr[nt2][ks], bst + boff + nt2 * 16 * BROW_B + ks * 32);

        // --- pre-barrier: A fragments ks=0 + MMA ks=0 (frees afr0 early) ---
        {
            uint32_t afr0[4][4];
            #pragma unroll
            for (int mi = 0; mi < 4; ++mi)
                ldm_x4(afr0[mi], a16b + aoff[mi]);
            #pragma unroll
            for (int mi = 0; mi < 4; ++mi)
                #pragma unroll
                for (int nt = 0; nt < 4; ++nt)
                    mma16816(acc[mi][nt], afr0[mi], &bfr[nt >> 1][0][(nt & 1) * 2]);
        }

        // --- pre-barrier: A fragments ks=1 ---
        uint32_t afr1[4][4];
        #pragma unroll
        for (int mi = 0; mi < 4; ++mi)
            ldm_x4(afr1[mi], a16b + aoff[mi] + 32);

        // --- pre-barrier: convert chunk it+1 into the other ping buffer ---
        if (it + 1 < SEG_CHUNKS) {
            int sn  = (s + 1 == STAGES) ? 0 : s + 1;
            int phn = (s + 1 == STAGES) ? (ph ^ 1) : ph;
            mbar_wait(MB + 8 * sn, phn);
            convert_chunk(smem + SM_A32 + sn * A32_BYTES,
                          smem + SM_A16 + ((it + 1) & 1) * A16_BYTES, tid);
        }

        __syncthreads();

        // --- post-barrier: refill stage s ---
        if (tid == 0) {
            int nxt = it + STAGES;
            if (nxt < SEG_CHUNKS) {
                mbar_expect_tx(MB + 8 * s, TXB);
                tma_2d(sb + SM_A32 + s * A32_BYTES, &tma_a, (c0 + nxt) * KC, m0g, MB + 8 * s);
                bulk_cp(sb + SM_B + s * BCHUNK_B, g_zh + (size_t)(c0 + nxt) * BCHUNK_H,
                        BCHUNK_B, MB + 8 * s);
            }
        }

        // --- post-barrier: MMA ks=1 (overlaps next iter's loads) ---
        #pragma unroll
        for (int mi = 0; mi < 4; ++mi)
            #pragma unroll
            for (int nt = 0; nt < 4; ++nt)
                mma16816(acc[mi][nt], afr1[mi], &bfr[nt >> 1][1][(nt & 1) * 2]);

        if (++s == STAGES) { s = 0; ph ^= 1; }
    }

    // --- epilogue: store raw fp32 partials ---
    float* part = g_part + (size_t)seg * NNODES * DIM;
    #pragma unroll
    for (int mi = 0; mi < 4; ++mi) {
        int r = m0w + mi * 16 + (lane >> 2);
        #pragma unroll
        for (int nt = 0; nt < 4; ++nt) {
            int c = n0w + nt * 8 + 2 * (lane & 3);
            size_t i0 = (size_t)(m0g + r) * DIM + c;
            const float* a = acc[mi][nt];
            *reinterpret_cast<float2*>(part + i0)           = make_float2(a[0], a[1]);
            *reinterpret_cast<float2*>(part + i0 + 8 * DIM) = make_float2(a[2], a[3]);
        }
    }
}

// ============================================================================
// Kernel 3 (combine): out = ReLU(p0+p1+p2+p3+u), elementwise float4.
// ============================================================================
__global__ __launch_bounds__(256) void combine_kernel(float* __restrict__ out) {
    const size_t i = (size_t)blockIdx.x * 256 + threadIdx.x;
    const size_t stride4 = (size_t)NNODES * DIM / 4;
    const float4* p = reinterpret_cast<const float4*>(g_part);
    const float4* uu = reinterpret_cast<const float4*>(g_u);
    float4 a0 = p[i], a1 = p[i + stride4], a2 = p[i + 2 * stride4], a3 = p[i + 3 * stride4];
    float4 u = uu[i];
    float4 o;
    o.x = fmaxf((a0.x + a1.x) + (a2.x + a3.x) + u.x, 0.f);
    o.y = fmaxf((a0.y + a1.y) + (a2.y + a3.y) + u.y, 0.f);
    o.z = fmaxf((a0.z + a1.z) + (a2.z + a3.z) + u.z, 0.f);
    o.w = fmaxf((a0.w + a1.w) + (a2.w + a3.w) + u.w, 0.f);
    reinterpret_cast<float4*>(out)[i] = o;
}

// ============================================================================
// Host launch
// ============================================================================
typedef CUresult (*EncodeFn)(CUtensorMap*, CUtensorMapDataType, cuuint32_t, void*,
                             const cuuint64_t*, const cuuint64_t*, const cuuint32_t*,
                             const cuuint32_t*, CUtensorMapInterleave, CUtensorMapSwizzle,
                             CUtensorMapL2promotion, CUtensorMapFloatOOBfill);

extern "C" void kernel_launch(void* const* d_in, const int* in_sizes, int n_in,
                              void* d_out, int out_size) {
    const float *x = nullptr, *adj = nullptr, *W = nullptr, *b = nullptr;
    for (int i = 0; i < n_in; ++i) {
        switch (in_sizes[i]) {
            case NNODES * DIM: x = (const float*)d_in[i]; break;
            case 32768:        W = (const float*)d_in[i]; break;
            case 128:          b = (const float*)d_in[i]; break;
            default:           adj = (const float*)d_in[i]; break;
        }
    }
    float* out = (float*)d_out;

    void* fn = nullptr;
    cudaDriverEntryPointQueryResult qr;
#if CUDART_VERSION >= 12050
    cudaGetDriverEntryPointByVersion("cuTensorMapEncodeTiled", &fn, 12000,
                                     cudaEnableDefault, &qr);
#else
    cudaGetDriverEntryPoint("cuTensorMapEncodeTiled", &fn, cudaEnableDefault, &qr);
#endif
    if (!fn) return;
    EncodeFn encode = (EncodeFn)fn;

    CUtensorMap mapA;
    {
        cuuint64_t dims[2]   = {NNODES, NNODES};
        cuuint64_t stride[1] = {NNODES * 4ull};
        cuuint32_t box[2]    = {KC, MTILE};        // 128B x 128 rows, SW128
        cuuint32_t es[2]     = {1, 1};
        encode(&mapA, CU_TENSOR_MAP_DATA_TYPE_FLOAT32, 2, (void*)adj, dims, stride, box, es,
               CU_TENSOR_MAP_INTERLEAVE_NONE, CU_TENSOR_MAP_SWIZZLE_128B,
               CU_TENSOR_MAP_L2_PROMOTION_L2_128B, CU_TENSOR_MAP_FLOAT_OOB_FILL_NONE);
    }

    cudaFuncSetAttribute(prep_kernel, cudaFuncAttributeMaxDynamicSharedMemorySize, PREP_SMEM);
    cudaFuncSetAttribute(gemm_kernel, cudaFuncAttributeMaxDynamicSharedMemorySize, GEMM_SMEM);

    prep_kernel<<<NNODES / 64, 256, PREP_SMEM>>>(x, W, b);
    gemm_kernel<<<(NNODES / MTILE) * KSPLIT, 256, GEMM_SMEM>>>(mapA);
    combine_kernel<<<(NNODES * DIM / 4) / 256, 256>>>(out);
}